// round 9
// baseline (speedup 1.0000x reference)
#include <cuda_runtime.h>
#include <math.h>

#define N_   8
#define C_   64
#define H_   256
#define W_   256
#define K2_  9
#define NBLK 512
#define QELEMS (H_ * W_ / 4)

// scratch (no cudaMalloc allowed); all counters monotonic => graph-replay safe
__device__ float g_part[N_ * C_ * 4];            // quarter-plane raw sums
__device__ unsigned int g_done[N_];              // pool completions per sample
__device__ unsigned int g_epoch_blk[NBLK];       // per-block replay counter

// ---------------------------------------------------------------------------
// Stencil for one 64-row x 256-col tile. Each warp: 4 tasks; a task is a
// 4-row x 128-col half-band. All 6 input rows preloaded (12+ independent LDG,
// MLP high) before SHFL/compute. Reflect padding resolved in-register.
// ---------------------------------------------------------------------------
__device__ __forceinline__ void stencil_tile(
        const float* __restrict__ x, float* __restrict__ out,
        int plane, int tile, int c, int warp, int lane,
        const float* wlf, const float* ps,
        const float* __restrict__ lamb_l,
        const float* __restrict__ lamb_h,
        const float* __restrict__ inside_all) {
    const size_t plane_off = (size_t)plane * (H_ * W_);
    const float* xp = x + plane_off;

    const float w0 = wlf[0], w1 = wlf[1], w2 = wlf[2];
    const float w3 = wlf[3], w4 = wlf[4], w5 = wlf[5];
    const float w6 = wlf[6], w7 = wlf[7], w8 = wlf[8];

    const float ll  = __ldg(lamb_l + c);
    const float lh1 = __ldg(lamb_h + c) + 1.f;
    const float ia  = __ldg(inside_all + c);
    const float A   = (ia + 1.f) * ll;
    const float Bc  = -ia * ps[c] * ll;

    #pragma unroll 1
    for (int i = 0; i < 4; ++i) {
        const int T    = warp * 4 + i;      // 0..31
        const int band = T >> 1;            // 0..15 -> 4-row band
        const int half = T & 1;             // 128-col half
        const int y0   = tile * 64 + band * 4;
        const int cb   = half * 128 + lane * 4;

        float win[6][6];
        #pragma unroll
        for (int r = 0; r < 6; ++r) {
            int g = y0 - 1 + r;
            g = g < 0 ? 1 : (g >= H_ ? 2 * H_ - 2 - g : g);
            const float* rp = xp + (size_t)g * W_;
            float4 v = __ldg((const float4*)(rp + cb));
            float  e = __ldg(rp + (half ? 127 : 128));   // uniform boundary scalar
            float lf = __shfl_up_sync(0xffffffffu, v.w, 1);
            float rt = __shfl_down_sync(0xffffffffu, v.x, 1);
            if (half == 0) {
                if (lane == 0)  lf = v.y;   // reflect col -1 -> col 1
                if (lane == 31) rt = e;     // col 128 from other half
            } else {
                if (lane == 0)  lf = e;     // col 127 from other half
                if (lane == 31) rt = v.z;   // reflect col 256 -> col 254
            }
            win[r][0] = lf;
            win[r][1] = v.x; win[r][2] = v.y; win[r][3] = v.z; win[r][4] = v.w;
            win[r][5] = rt;
        }

        float* ob = out + plane_off + (size_t)y0 * W_ + cb;
        #pragma unroll
        for (int k = 0; k < 4; ++k) {
            float o[4];
            #pragma unroll
            for (int j = 0; j < 4; ++j) {
                float acc;
                acc = w0 * win[k][j];
                acc = fmaf(w1, win[k][j + 1], acc);
                acc = fmaf(w2, win[k][j + 2], acc);
                acc = fmaf(w3, win[k + 1][j],     acc);
                acc = fmaf(w4, win[k + 1][j + 1], acc);
                acc = fmaf(w5, win[k + 1][j + 2], acc);
                acc = fmaf(w6, win[k + 2][j],     acc);
                acc = fmaf(w7, win[k + 2][j + 1], acc);
                acc = fmaf(w8, win[k + 2][j + 2], acc);
                o[j] = fmaf(acc, A, fmaf(win[k + 1][j + 1], lh1, Bc));
            }
            __stcs((float4*)(ob + (size_t)k * W_),
                   make_float4(o[0], o[1], o[2], o[3]));
        }
    }
}

// ---------------------------------------------------------------------------
// Group-decoupled pipeline: block group g (64 blocks) owns sample g entirely.
// Pool 4 quarter-planes -> group-local wait -> lf once -> 4 stencil tiles.
// No grid-wide synchronization anywhere.
// ---------------------------------------------------------------------------
__global__ __launch_bounds__(256, 4) void fused_kernel(
        const float* __restrict__ x,
        const float* __restrict__ conv_w,
        const float* __restrict__ bn_gamma,
        const float* __restrict__ bn_beta,
        const float* __restrict__ bn_mean,
        const float* __restrict__ bn_var,
        const float* __restrict__ lamb_l,
        const float* __restrict__ lamb_h,
        const float* __restrict__ inside_all,
        float* __restrict__ out) {
    const int b    = blockIdx.x;
    const int g    = b >> 6;          // sample / group id
    const int r    = b & 63;          // rank within group
    const int tid  = threadIdx.x;
    const int warp = tid >> 5;
    const int lane = tid & 31;

    __shared__ float ws[8];
    __shared__ float ps[C_];
    __shared__ float wlf[4][K2_];

    unsigned int target = 0;
    if (tid == 0)
        target = (atomicAdd(&g_epoch_blk[b], 1u) + 1u) * 256u;

    // ---- pool: 4 quarter-plane items of sample g ---------------------------
    #pragma unroll 1
    for (int k = 0; k < 4; ++k) {
        const int item = g * 256 + r + 64 * k;
        const float4* xv = (const float4*)(x + (size_t)item * QELEMS);
        float s = 0.f;
        #pragma unroll
        for (int i = 0; i < 16; ++i) {
            float4 v = __ldg(&xv[tid + i * 256]);
            s += (v.x + v.y) + (v.z + v.w);
        }
        #pragma unroll
        for (int o = 16; o; o >>= 1) s += __shfl_down_sync(0xffffffffu, s, o);
        if (lane == 0) ws[warp] = s;
        __syncthreads();
        if (tid == 0)
            g_part[item] = ws[0] + ws[1] + ws[2] + ws[3]
                         + ws[4] + ws[5] + ws[6] + ws[7];
        __syncthreads();
    }

    // ---- group-local release + wait (64 blocks only) -----------------------
    if (tid == 0) {
        __threadfence();
        atomicAdd(&g_done[g], 4u);
        while (*((volatile unsigned int*)&g_done[g]) < target)
            __nanosleep(32);
    }
    __syncthreads();
    __threadfence();

    // ---- lf weights (once per block, covers its 4 stencil items) -----------
    if (tid < C_) {
        const float* p = g_part + (g * C_ + tid) * 4;
        ps[tid] = (__ldcg(p) + __ldcg(p + 1) + __ldcg(p + 2) + __ldcg(p + 3))
                  * (1.f / (H_ * W_));
    }
    __syncthreads();
    if (tid < 36) {
        const int k  = tid / 9;
        const int t9 = tid - 9 * k;
        const int c  = (r >> 2) + 16 * k;
        const int jj = (c >> 3) * K2_ + t9;
        const float* wv = conv_w + jj * C_;
        float acc = 0.f;
        #pragma unroll
        for (int cc = 0; cc < C_; ++cc) acc = fmaf(ps[cc], wv[cc], acc);
        const float inv = rsqrtf(bn_var[jj] + 1e-5f);
        const float v = (acc - bn_mean[jj]) * (bn_gamma[jj] * inv) + bn_beta[jj];
        wlf[k][t9] = tanhf(v);
    }
    __syncthreads();

    // ---- 4 stencil tiles, no further syncs ----------------------------------
    #pragma unroll 1
    for (int k = 0; k < 4; ++k) {
        const int c     = (r >> 2) + 16 * k;
        const int plane = g * C_ + c;
        const int tile  = r & 3;
        stencil_tile(x, out, plane, tile, c, warp, lane,
                     wlf[k], ps, lamb_l, lamb_h, inside_all);
    }
}

// ---------------------------------------------------------------------------
extern "C" void kernel_launch(void* const* d_in, const int* in_sizes, int n_in,
                              void* d_out, int out_size) {
    const float* x          = (const float*)d_in[0];
    const float* conv_w     = (const float*)d_in[1];
    const float* bn_gamma   = (const float*)d_in[2];
    const float* bn_beta    = (const float*)d_in[3];
    const float* bn_mean    = (const float*)d_in[4];
    const float* bn_var     = (const float*)d_in[5];
    const float* lamb_l     = (const float*)d_in[6];
    const float* lamb_h     = (const float*)d_in[7];
    const float* inside_all = (const float*)d_in[8];
    float* out = (float*)d_out;

    fused_kernel<<<NBLK, 256>>>(x, conv_w, bn_gamma, bn_beta, bn_mean, bn_var,
                                lamb_l, lamb_h, inside_all, out);
}

// round 10
// speedup vs baseline: 1.1177x; 1.1177x over previous
#include <cuda_runtime.h>
#include <math.h>

#define N_   8
#define C_   64
#define H_   256
#define W_   256
#define K2_  9
#define NBLK 512
#define QELEMS (H_ * W_ / 4)

// scratch (no cudaMalloc allowed); all counters monotonic => graph-replay safe
__device__ float g_part[N_ * C_ * 4];            // quarter-plane raw sums
__device__ unsigned int g_done[N_];              // pool completions per sample
__device__ unsigned int g_epoch_blk[NBLK];       // per-block replay counter

// ---------------------------------------------------------------------------
// Stencil for one 64-row x 256-col tile. Each warp: 4 tasks; a task is a
// 4-row x 128-col half-band. All 6 input rows preloaded (12+ independent LDG,
// MLP high) before SHFL/compute. Reflect padding resolved in-register.
// ---------------------------------------------------------------------------
__device__ __forceinline__ void stencil_tile(
        const float* __restrict__ x, float* __restrict__ out,
        int plane, int tile, int c, int warp, int lane,
        const float* wlf, const float* ps,
        const float* __restrict__ lamb_l,
        const float* __restrict__ lamb_h,
        const float* __restrict__ inside_all) {
    const size_t plane_off = (size_t)plane * (H_ * W_);
    const float* xp = x + plane_off;

    const float w0 = wlf[0], w1 = wlf[1], w2 = wlf[2];
    const float w3 = wlf[3], w4 = wlf[4], w5 = wlf[5];
    const float w6 = wlf[6], w7 = wlf[7], w8 = wlf[8];

    const float ll  = __ldg(lamb_l + c);
    const float lh1 = __ldg(lamb_h + c) + 1.f;
    const float ia  = __ldg(inside_all + c);
    const float A   = (ia + 1.f) * ll;
    const float Bc  = -ia * ps[c] * ll;

    #pragma unroll 1
    for (int i = 0; i < 4; ++i) {
        const int T    = warp * 4 + i;      // 0..31
        const int band = T >> 1;            // 0..15 -> 4-row band
        const int half = T & 1;             // 128-col half
        const int y0   = tile * 64 + band * 4;
        const int cb   = half * 128 + lane * 4;

        float win[6][6];
        #pragma unroll
        for (int r = 0; r < 6; ++r) {
            int g = y0 - 1 + r;
            g = g < 0 ? 1 : (g >= H_ ? 2 * H_ - 2 - g : g);
            const float* rp = xp + (size_t)g * W_;
            float4 v = __ldg((const float4*)(rp + cb));
            float  e = __ldg(rp + (half ? 127 : 128));   // uniform boundary scalar
            float lf = __shfl_up_sync(0xffffffffu, v.w, 1);
            float rt = __shfl_down_sync(0xffffffffu, v.x, 1);
            if (half == 0) {
                if (lane == 0)  lf = v.y;   // reflect col -1 -> col 1
                if (lane == 31) rt = e;     // col 128 from other half
            } else {
                if (lane == 0)  lf = e;     // col 127 from other half
                if (lane == 31) rt = v.z;   // reflect col 256 -> col 254
            }
            win[r][0] = lf;
            win[r][1] = v.x; win[r][2] = v.y; win[r][3] = v.z; win[r][4] = v.w;
            win[r][5] = rt;
        }

        float* ob = out + plane_off + (size_t)y0 * W_ + cb;
        #pragma unroll
        for (int k = 0; k < 4; ++k) {
            float o[4];
            #pragma unroll
            for (int j = 0; j < 4; ++j) {
                float acc;
                acc = w0 * win[k][j];
                acc = fmaf(w1, win[k][j + 1], acc);
                acc = fmaf(w2, win[k][j + 2], acc);
                acc = fmaf(w3, win[k + 1][j],     acc);
                acc = fmaf(w4, win[k + 1][j + 1], acc);
                acc = fmaf(w5, win[k + 1][j + 2], acc);
                acc = fmaf(w6, win[k + 2][j],     acc);
                acc = fmaf(w7, win[k + 2][j + 1], acc);
                acc = fmaf(w8, win[k + 2][j + 2], acc);
                o[j] = fmaf(acc, A, fmaf(win[k + 1][j + 1], lh1, Bc));
            }
            __stcs((float4*)(ob + (size_t)k * W_),
                   make_float4(o[0], o[1], o[2], o[3]));
        }
    }
}

// ---------------------------------------------------------------------------
// Group-decoupled pipeline: block group g (64 blocks) owns sample g entirely.
// Pool quarters in order k=0..3, then stencil in LIFO order k=3..0 so the
// hottest-in-L2 quarter is consumed first (recency-optimal vs eviction).
// ---------------------------------------------------------------------------
__global__ __launch_bounds__(256, 4) void fused_kernel(
        const float* __restrict__ x,
        const float* __restrict__ conv_w,
        const float* __restrict__ bn_gamma,
        const float* __restrict__ bn_beta,
        const float* __restrict__ bn_mean,
        const float* __restrict__ bn_var,
        const float* __restrict__ lamb_l,
        const float* __restrict__ lamb_h,
        const float* __restrict__ inside_all,
        float* __restrict__ out) {
    const int b    = blockIdx.x;
    const int g    = b >> 6;          // sample / group id
    const int r    = b & 63;          // rank within group
    const int tid  = threadIdx.x;
    const int warp = tid >> 5;
    const int lane = tid & 31;

    __shared__ float ws[8];
    __shared__ float ps[C_];
    __shared__ float wlf[4][K2_];

    unsigned int target = 0;
    if (tid == 0)
        target = (atomicAdd(&g_epoch_blk[b], 1u) + 1u) * 256u;

    // ---- pool: 4 quarter-plane items of sample g (k = 0..3) ----------------
    #pragma unroll 1
    for (int k = 0; k < 4; ++k) {
        const int item = g * 256 + r + 64 * k;
        const float4* xv = (const float4*)(x + (size_t)item * QELEMS);
        float s = 0.f;
        #pragma unroll
        for (int i = 0; i < 16; ++i) {
            float4 v = __ldg(&xv[tid + i * 256]);
            s += (v.x + v.y) + (v.z + v.w);
        }
        #pragma unroll
        for (int o = 16; o; o >>= 1) s += __shfl_down_sync(0xffffffffu, s, o);
        if (lane == 0) ws[warp] = s;
        __syncthreads();
        if (tid == 0)
            g_part[item] = ws[0] + ws[1] + ws[2] + ws[3]
                         + ws[4] + ws[5] + ws[6] + ws[7];
        __syncthreads();
    }

    // ---- group-local release + wait (64 blocks only) -----------------------
    if (tid == 0) {
        __threadfence();
        atomicAdd(&g_done[g], 4u);
        while (*((volatile unsigned int*)&g_done[g]) < target)
            __nanosleep(32);
    }
    __syncthreads();
    __threadfence();

    // ---- lf weights (once per block, covers its 4 stencil items) -----------
    if (tid < C_) {
        const float* p = g_part + (g * C_ + tid) * 4;
        ps[tid] = (__ldcg(p) + __ldcg(p + 1) + __ldcg(p + 2) + __ldcg(p + 3))
                  * (1.f / (H_ * W_));
    }
    __syncthreads();
    if (tid < 36) {
        const int k  = tid / 9;
        const int t9 = tid - 9 * k;
        const int c  = (r >> 2) + 16 * k;
        const int jj = (c >> 3) * K2_ + t9;
        const float* wv = conv_w + jj * C_;
        float acc = 0.f;
        #pragma unroll
        for (int cc = 0; cc < C_; ++cc) acc = fmaf(ps[cc], wv[cc], acc);
        const float inv = rsqrtf(bn_var[jj] + 1e-5f);
        const float v = (acc - bn_mean[jj]) * (bn_gamma[jj] * inv) + bn_beta[jj];
        wlf[k][t9] = tanhf(v);
    }
    __syncthreads();

    // ---- 4 stencil tiles, LIFO over pooled quarters (k = 3..0) -------------
    #pragma unroll 1
    for (int k = 3; k >= 0; --k) {
        const int c     = (r >> 2) + 16 * k;
        const int plane = g * C_ + c;
        const int tile  = r & 3;
        stencil_tile(x, out, plane, tile, c, warp, lane,
                     wlf[k], ps, lamb_l, lamb_h, inside_all);
    }
}

// ---------------------------------------------------------------------------
extern "C" void kernel_launch(void* const* d_in, const int* in_sizes, int n_in,
                              void* d_out, int out_size) {
    const float* x          = (const float*)d_in[0];
    const float* conv_w     = (const float*)d_in[1];
    const float* bn_gamma   = (const float*)d_in[2];
    const float* bn_beta    = (const float*)d_in[3];
    const float* bn_mean    = (const float*)d_in[4];
    const float* bn_var     = (const float*)d_in[5];
    const float* lamb_l     = (const float*)d_in[6];
    const float* lamb_h     = (const float*)d_in[7];
    const float* inside_all = (const float*)d_in[8];
    float* out = (float*)d_out;

    fused_kernel<<<NBLK, 256>>>(x, conv_w, bn_gamma, bn_beta, bn_mean, bn_var,
                                lamb_l, lamb_h, inside_all, out);
}